// round 1
// baseline (speedup 1.0000x reference)
#include <cuda_runtime.h>
#include <math.h>
#include <stdint.h>

#define B_    256
#define G_    16
#define GS_   588
#define HID_  1024
#define FEAT_ 2048
#define NSPLIT 16
#define KSPLIT ((G_ * FEAT_) / NSPLIT)   // 32768/16 = 2048

#define BM 128
#define BN 128
#define BK 8

// ---------------- scratch (device globals; no runtime alloc) ----------------
__device__ float g_h[(size_t)2 * B_ * G_ * HID_];        // [br*256+b][16384]
__device__ float g_f[(size_t)2 * B_ * G_ * FEAT_];       // [512][32768] interleaved o*16+g
__device__ float g_part[(size_t)NSPLIT * 2 * B_ * HID_]; // [split][512][1024]
__device__ float g_hg[(size_t)2 * B_ * HID_];            // [512][1024]
__device__ float g_o[(size_t)2 * B_ * FEAT_];            // [512][2048]
__device__ float g_scores[B_];

__device__ __forceinline__ float silu_f(float v) {
    return v / (1.0f + expf(-v));
}

// ---------------- shared 128x128x8 fp32 GEMM tile body ----------------
// A: [M,K] row-major (row stride lda), W: [K,N] row-major (row stride ldw).
// Computes acc[i][j] = sum_k A[m0+ty*8+i][k] * W[k][n0+tx*8+j].
__device__ __forceinline__ void sgemm_tile(
    const float* __restrict__ A, int lda,
    const float* __restrict__ W, int ldw,
    int K, int m0, int n0, float acc[8][8])
{
    __shared__ float As[BK][BM];
    __shared__ float Ws[BK][BN];

    const int tid  = threadIdx.x;      // 256 threads
    const int arow = tid >> 1;         // 0..127
    const int acol = (tid & 1) << 2;   // 0 or 4
    const int wrow = tid >> 5;         // 0..7
    const int wcol = (tid & 31) << 2;  // 0..124
    const int tx   = tid & 15;
    const int ty   = tid >> 4;

    const float* Aptr = A + (size_t)(m0 + arow) * lda;

    for (int k0 = 0; k0 < K; k0 += BK) {
        // load A sub-tile 128x8 (scalar, handles K not multiple of 8 / unaligned)
        #pragma unroll
        for (int i = 0; i < 4; ++i) {
            int kk = acol + i;
            int kg = k0 + kk;
            float v = 0.0f;
            if (kg < K) v = Aptr[kg];
            As[kk][arow] = v;
        }
        // load W sub-tile 8x128 (vectorized, coalesced)
        {
            float4 wv = make_float4(0.f, 0.f, 0.f, 0.f);
            if (k0 + wrow < K)
                wv = *reinterpret_cast<const float4*>(
                        W + (size_t)(k0 + wrow) * ldw + n0 + wcol);
            Ws[wrow][wcol + 0] = wv.x;
            Ws[wrow][wcol + 1] = wv.y;
            Ws[wrow][wcol + 2] = wv.z;
            Ws[wrow][wcol + 3] = wv.w;
        }
        __syncthreads();

        #pragma unroll
        for (int kk = 0; kk < BK; ++kk) {
            float ra[8], rb[8];
            #pragma unroll
            for (int i = 0; i < 8; ++i) ra[i] = As[kk][ty * 8 + i];
            #pragma unroll
            for (int j = 0; j < 8; ++j) rb[j] = Ws[kk][tx * 8 + j];
            #pragma unroll
            for (int i = 0; i < 8; ++i)
                #pragma unroll
                for (int j = 0; j < 8; ++j)
                    acc[i][j] = fmaf(ra[i], rb[j], acc[i][j]);
        }
        __syncthreads();
    }
}

// ---------------- stage 1: grouped fc1 (q & k branches) ----------------
// grid (2, 8, 32): z = branch*16 + group
__global__ __launch_bounds__(256) void k_grouped_fc1(
    const float* __restrict__ q,  const float* __restrict__ k,
    const float* __restrict__ Wq1, const float* __restrict__ bq1,
    const float* __restrict__ Wk1, const float* __restrict__ bk1)
{
    const int z  = blockIdx.z;
    const int br = z >> 4;
    const int g  = z & 15;

    const float* x    = (br ? k : q) + g * GS_;
    const float* W    = (br ? Wk1 : Wq1) + (size_t)g * GS_ * HID_;
    const float* bias = (br ? bk1 : bq1) + g * HID_;

    float acc[8][8];
    #pragma unroll
    for (int i = 0; i < 8; ++i)
        #pragma unroll
        for (int j = 0; j < 8; ++j) acc[i][j] = 0.0f;

    const int m0 = blockIdx.x * BM;
    const int n0 = blockIdx.y * BN;
    sgemm_tile(x, G_ * GS_, W, HID_, GS_, m0, n0, acc);

    float* C = g_h + (size_t)br * B_ * G_ * HID_ + g * HID_;
    const int tx = threadIdx.x & 15, ty = threadIdx.x >> 4;
    #pragma unroll
    for (int i = 0; i < 8; ++i) {
        int row = m0 + ty * 8 + i;
        #pragma unroll
        for (int j = 0; j < 8; ++j) {
            int col = n0 + tx * 8 + j;
            float v = acc[i][j] + bias[col];
            C[(size_t)row * (G_ * HID_) + col] = silu_f(v);
        }
    }
}

// ---------------- stage 2: grouped fc4 + interleaved store ----------------
// grid (2, 16, 32)
__global__ __launch_bounds__(256) void k_grouped_fc4(
    const float* __restrict__ Wq4, const float* __restrict__ bq4,
    const float* __restrict__ Wk4, const float* __restrict__ bk4)
{
    const int z  = blockIdx.z;
    const int br = z >> 4;
    const int g  = z & 15;

    const float* A    = g_h + (size_t)br * B_ * G_ * HID_ + g * HID_;
    const float* W    = (br ? Wk4 : Wq4) + (size_t)g * HID_ * FEAT_;
    const float* bias = (br ? bk4 : bq4) + g * FEAT_;

    float acc[8][8];
    #pragma unroll
    for (int i = 0; i < 8; ++i)
        #pragma unroll
        for (int j = 0; j < 8; ++j) acc[i][j] = 0.0f;

    const int m0 = blockIdx.x * BM;
    const int n0 = blockIdx.y * BN;
    sgemm_tile(A, G_ * HID_, W, FEAT_, HID_, m0, n0, acc);

    // qf[b, o*G + g] = silu(f[b,g,o])  (feature-major interleave)
    const int tx = threadIdx.x & 15, ty = threadIdx.x >> 4;
    #pragma unroll
    for (int i = 0; i < 8; ++i) {
        int row = m0 + ty * 8 + i;
        size_t rbase = (size_t)(br * B_ + row) * (G_ * FEAT_);
        #pragma unroll
        for (int j = 0; j < 8; ++j) {
            int col = n0 + tx * 8 + j;
            float v = acc[i][j] + bias[col];
            g_f[rbase + (size_t)col * G_ + g] = silu_f(v);
        }
    }
}

// ---------------- stage 3: global fc1, split-K (deterministic) ----------------
// grid (4, 8, NSPLIT): M=512 (q rows 0..255, k rows 256..511)
__global__ __launch_bounds__(256) void k_global_fc1_splitk(
    const float* __restrict__ Wg1)
{
    const int s = blockIdx.z;
    const float* A = g_f + s * KSPLIT;
    const float* W = Wg1 + (size_t)s * KSPLIT * HID_;

    float acc[8][8];
    #pragma unroll
    for (int i = 0; i < 8; ++i)
        #pragma unroll
        for (int j = 0; j < 8; ++j) acc[i][j] = 0.0f;

    const int m0 = blockIdx.x * BM;
    const int n0 = blockIdx.y * BN;
    sgemm_tile(A, G_ * FEAT_, W, HID_, KSPLIT, m0, n0, acc);

    float* P = g_part + (size_t)s * (2 * B_ * HID_);
    const int tx = threadIdx.x & 15, ty = threadIdx.x >> 4;
    #pragma unroll
    for (int i = 0; i < 8; ++i) {
        int row = m0 + ty * 8 + i;
        #pragma unroll
        for (int j = 0; j < 8; ++j) {
            int col = n0 + tx * 8 + j;
            P[(size_t)row * HID_ + col] = acc[i][j];
        }
    }
}

// reduce NSPLIT partials + bias + silu -> g_hg
__global__ __launch_bounds__(256) void k_reduce_silu(const float* __restrict__ bg1)
{
    int idx = blockIdx.x * blockDim.x + threadIdx.x;   // 0 .. 512*1024-1
    if (idx >= 2 * B_ * HID_) return;
    int col = idx & (HID_ - 1);
    float v = bg1[col];
    #pragma unroll
    for (int s = 0; s < NSPLIT; ++s)
        v += g_part[(size_t)s * (2 * B_ * HID_) + idx];
    g_hg[idx] = silu_f(v);
}

// ---------------- stage 4: global fc4 ----------------
// grid (4, 16)
__global__ __launch_bounds__(256) void k_global_fc4(
    const float* __restrict__ Wg4, const float* __restrict__ bg4)
{
    float acc[8][8];
    #pragma unroll
    for (int i = 0; i < 8; ++i)
        #pragma unroll
        for (int j = 0; j < 8; ++j) acc[i][j] = 0.0f;

    const int m0 = blockIdx.x * BM;
    const int n0 = blockIdx.y * BN;
    sgemm_tile(g_hg, HID_, Wg4, FEAT_, HID_, m0, n0, acc);

    const int tx = threadIdx.x & 15, ty = threadIdx.x >> 4;
    #pragma unroll
    for (int i = 0; i < 8; ++i) {
        int row = m0 + ty * 8 + i;
        #pragma unroll
        for (int j = 0; j < 8; ++j) {
            int col = n0 + tx * 8 + j;
            float v = acc[i][j] + bg4[col];
            g_o[(size_t)row * FEAT_ + col] = silu_f(v);
        }
    }
}

// ---------------- stage 5: per-batch dot ----------------
__global__ __launch_bounds__(256) void k_dot()
{
    const int b = blockIdx.x;
    const int t = threadIdx.x;
    const float* qo = g_o + (size_t)b * FEAT_;
    const float* ko = g_o + (size_t)(B_ + b) * FEAT_;
    float s = 0.0f;
    for (int i = t; i < FEAT_; i += 256)
        s = fmaf(qo[i], ko[i], s);
    __shared__ float sh[256];
    sh[t] = s;
    __syncthreads();
    for (int off = 128; off > 0; off >>= 1) {
        if (t < off) sh[t] += sh[t + off];
        __syncthreads();
    }
    if (t == 0) g_scores[b] = sh[0];
}

// ---------------- stage 6: softmax over batch ----------------
__global__ __launch_bounds__(256) void k_softmax(float* __restrict__ out)
{
    const int t = threadIdx.x;
    __shared__ float sh[256];
    float v = g_scores[t];
    sh[t] = v;
    __syncthreads();
    for (int off = 128; off > 0; off >>= 1) {
        if (t < off) sh[t] = fmaxf(sh[t], sh[t + off]);
        __syncthreads();
    }
    float m = sh[0];
    __syncthreads();
    float e = expf(v - m);
    sh[t] = e;
    __syncthreads();
    for (int off = 128; off > 0; off >>= 1) {
        if (t < off) sh[t] += sh[t + off];
        __syncthreads();
    }
    out[t] = e / sh[0];
}

// ---------------- launch ----------------
extern "C" void kernel_launch(void* const* d_in, const int* in_sizes, int n_in,
                              void* d_out, int out_size)
{
    const float* q   = (const float*)d_in[0];
    const float* k   = (const float*)d_in[1];
    const float* Wq1 = (const float*)d_in[2];
    const float* bq1 = (const float*)d_in[3];
    const float* Wq4 = (const float*)d_in[4];
    const float* bq4 = (const float*)d_in[5];
    const float* Wk1 = (const float*)d_in[6];
    const float* bk1 = (const float*)d_in[7];
    const float* Wk4 = (const float*)d_in[8];
    const float* bk4 = (const float*)d_in[9];
    const float* Wg1 = (const float*)d_in[10];
    const float* bg1 = (const float*)d_in[11];
    const float* Wg4 = (const float*)d_in[12];
    const float* bg4 = (const float*)d_in[13];
    float* out = (float*)d_out;

    k_grouped_fc1<<<dim3(B_ / BM, HID_ / BN, 2 * G_), 256>>>(q, k, Wq1, bq1, Wk1, bk1);
    k_grouped_fc4<<<dim3(B_ / BM, FEAT_ / BN, 2 * G_), 256>>>(Wq4, bq4, Wk4, bk4);
    k_global_fc1_splitk<<<dim3((2 * B_) / BM, HID_ / BN, NSPLIT), 256>>>(Wg1);
    k_reduce_silu<<<(2 * B_ * HID_) / 256, 256>>>(bg1);
    k_global_fc4<<<dim3((2 * B_) / BM, FEAT_ / BN, 1), 256>>>(Wg4, bg4);
    k_dot<<<B_, 256>>>();
    k_softmax<<<1, 256>>>(out);
}